// round 17
// baseline (speedup 1.0000x reference)
#include <cuda_runtime.h>

#define cB 2
#define cN 2048
#define cDIM 1024
#define cH 16
#define cD 64
#define cE 3072      // 3*DIM
#define cM 4096      // B*N
#define cK 1024

// Scratch: q,k,v in [B,H,N,D] layout (16 MB each); q/k stored UN-normalized
__device__ float g_q[cB * cH * cN * cD];
__device__ float g_k[cB * cH * cN * cD];
__device__ float g_v[cB * cH * cN * cD];

// ---- tf32 helpers ----------------------------------------------------------
__device__ __forceinline__ unsigned f2tf32(float x) {
    unsigned r;
    asm("cvt.rna.tf32.f32 %0, %1;" : "=r"(r) : "f"(x));
    return r;
}
// D += A * B  (m16n8k8 tf32)
__device__ __forceinline__ void mma_tf32(float* cc, const unsigned* a,
                                         unsigned b0, unsigned b1) {
    asm volatile(
        "mma.sync.aligned.m16n8k8.row.col.f32.tf32.tf32.f32 "
        "{%0,%1,%2,%3}, {%4,%5,%6,%7}, {%8,%9}, {%0,%1,%2,%3};"
        : "+f"(cc[0]), "+f"(cc[1]), "+f"(cc[2]), "+f"(cc[3])
        : "r"(a[0]), "r"(a[1]), "r"(a[2]), "r"(a[3]), "r"(b0), "r"(b1));
}

// ---------------------------------------------------------------------------
// Kernel 1: qkv = x @ W^T + b via split-tf32 mma, fragment-plane smem,
// now DOUBLE-BUFFERED: convert of tile k+1 issued after this iter's mma,
// one __syncthreads per iteration -> STS/convert overlaps tensor work.
// CTA 128m x 128e, BK=16, 8 warps (2m x 4n), warp tile 64x32, 2 CTAs/SM.
// 3-term split tf32: D += Ahi*Bhi + Ahi*Blo + Alo*Bhi (~2^-22 rel error).
// ---------------------------------------------------------------------------
#define APL 552    // A plane stride, 552 % 32 == 8
#define BPL 1064   // B plane stride, 1064 % 32 == 8
#define GBUF (8 * APL + 4 * BPL)   // 8672 words per buffer

__global__ __launch_bounds__(256, 2) void qkv_gemm(const float* __restrict__ x,
                                                   const float* __restrict__ wgt,
                                                   const float* __restrict__ bias) {
    extern __shared__ float smg[];   // 2 * GBUF words = 69376 B

    const int tid  = threadIdx.x;
    const int lane = tid & 31;
    const int wrp  = tid >> 5;
    const int wm   = wrp >> 2;
    const int wn   = wrp & 3;
    const int g    = lane >> 2;
    const int c    = lane & 3;
    const int m0   = blockIdx.y * 128;
    const int e0   = blockIdx.x * 128;

    const int lr  = tid >> 2;
    const int lc4 = (tid & 3) * 4;
    const float* xp = x   + (size_t)(m0 + lr) * cK + lc4;
    const float* wp = wgt + (size_t)(e0 + lr) * cK + lc4;

    const int skc = lc4 >> 3;
    const int skh = (lc4 & 7) >> 2;

    // Precomputed store coords (A reps 0/1, B reps 0/1)
    int awb[2], aj;
    {
        aj = ((lr >> 3) & 1) + 2 * skh;
#pragma unroll
        for (int rep = 0; rep < 2; rep++) {
            int row = lr + rep * 64;
            awb[rep] = (skc * 8 + (row >> 4)) * 33 + (row & 7);
        }
    }
    int bwb[2];
#pragma unroll
    for (int rep = 0; rep < 2; rep++) {
        int n = lr + rep * 64;
        bwb[rep] = (skc * 16 + (n >> 3)) * 33 + (n & 7);
    }
    const int bpl = skh;

    float acc[4][4][4];
#pragma unroll
    for (int mb = 0; mb < 4; mb++)
#pragma unroll
        for (int nt = 0; nt < 4; nt++)
#pragma unroll
            for (int i = 0; i < 4; i++) acc[mb][nt][i] = 0.f;

    float4 pa0 = *(const float4*)(xp);
    float4 pa1 = *(const float4*)(xp + (size_t)64 * cK);
    float4 pb0 = *(const float4*)(wp);
    float4 pb1 = *(const float4*)(wp + (size_t)64 * cK);

    // ---- convert tile 0 into buffer 0 ----
    {
        float* Aw = smg;
        float* Bw = smg + 8 * APL;
        float va[2][4] = {{pa0.x, pa0.y, pa0.z, pa0.w},
                          {pa1.x, pa1.y, pa1.z, pa1.w}};
        float vb[2][4] = {{pb0.x, pb0.y, pb0.z, pb0.w},
                          {pb1.x, pb1.y, pb1.z, pb1.w}};
#pragma unroll
        for (int rep = 0; rep < 2; rep++) {
#pragma unroll
            for (int i = 0; i < 4; i++) {
                unsigned hb = f2tf32(va[rep][i]);
                unsigned lb = f2tf32(va[rep][i] - __uint_as_float(hb));
                Aw[aj * APL + awb[rep] + 8 * i]       = __uint_as_float(hb);
                Aw[(4 + aj) * APL + awb[rep] + 8 * i] = __uint_as_float(lb);
                hb = f2tf32(vb[rep][i]);
                lb = f2tf32(vb[rep][i] - __uint_as_float(hb));
                Bw[bpl * BPL + bwb[rep] + 8 * i]       = __uint_as_float(hb);
                Bw[(2 + bpl) * BPL + bwb[rep] + 8 * i] = __uint_as_float(lb);
            }
        }
    }
    __syncthreads();

    int buf = 0;
    for (int kt = 0; kt < cK; kt += 16) {
        const float* Ab = smg + buf * GBUF;
        const float* Bb = Ab + 8 * APL;
        const bool more = (kt + 16 < cK);
        if (more) {
            pa0 = *(const float4*)(xp + kt + 16);
            pa1 = *(const float4*)(xp + (size_t)64 * cK + kt + 16);
            pb0 = *(const float4*)(wp + kt + 16);
            pb1 = *(const float4*)(wp + (size_t)64 * cK + kt + 16);
        }

#pragma unroll
        for (int kc = 0; kc < 2; kc++) {
            unsigned bh0[4], bh1[4], bl0[4], bl1[4];
#pragma unroll
            for (int nt = 0; nt < 4; nt++) {
                int off = (kc * 16 + wn * 4 + nt) * 33 + g + 8 * c;
                bh0[nt] = __float_as_uint(Bb[off]);
                bh1[nt] = __float_as_uint(Bb[BPL + off]);
                bl0[nt] = __float_as_uint(Bb[2 * BPL + off]);
                bl1[nt] = __float_as_uint(Bb[3 * BPL + off]);
            }
#pragma unroll
            for (int mb = 0; mb < 4; mb++) {
                int aoff = (kc * 8 + wm * 4 + mb) * 33 + c * 8 + g;
                unsigned ah[4], al[4];
#pragma unroll
                for (int j = 0; j < 4; j++) {
                    ah[j] = __float_as_uint(Ab[j * APL + aoff]);
                    al[j] = __float_as_uint(Ab[(4 + j) * APL + aoff]);
                }
#pragma unroll
                for (int nt = 0; nt < 4; nt++) {
                    mma_tf32(acc[mb][nt], ah, bh0[nt], bh1[nt]);
                    mma_tf32(acc[mb][nt], ah, bl0[nt], bl1[nt]);
                    mma_tf32(acc[mb][nt], al, bh0[nt], bh1[nt]);
                }
            }
        }

        if (more) {
            float* Aw = smg + (buf ^ 1) * GBUF;
            float* Bw = Aw + 8 * APL;
            float va[2][4] = {{pa0.x, pa0.y, pa0.z, pa0.w},
                              {pa1.x, pa1.y, pa1.z, pa1.w}};
            float vb[2][4] = {{pb0.x, pb0.y, pb0.z, pb0.w},
                              {pb1.x, pb1.y, pb1.z, pb1.w}};
#pragma unroll
            for (int rep = 0; rep < 2; rep++) {
#pragma unroll
                for (int i = 0; i < 4; i++) {
                    unsigned hb = f2tf32(va[rep][i]);
                    unsigned lb = f2tf32(va[rep][i] - __uint_as_float(hb));
                    Aw[aj * APL + awb[rep] + 8 * i]       = __uint_as_float(hb);
                    Aw[(4 + aj) * APL + awb[rep] + 8 * i] = __uint_as_float(lb);
                    hb = f2tf32(vb[rep][i]);
                    lb = f2tf32(vb[rep][i] - __uint_as_float(hb));
                    Bw[bpl * BPL + bwb[rep] + 8 * i]       = __uint_as_float(hb);
                    Bw[(2 + bpl) * BPL + bwb[rep] + 8 * i] = __uint_as_float(lb);
                }
            }
            __syncthreads();
        }
        buf ^= 1;
    }

    // Epilogue: bias + scatter into q/k/v [B,H,N,D] (raw, un-normalized).
#pragma unroll
    for (int mb = 0; mb < 4; mb++) {
#pragma unroll
        for (int hr = 0; hr < 2; hr++) {
            int m  = m0 + wm * 64 + mb * 16 + g + hr * 8;
            int bb = m >> 11;
            int n  = m & (cN - 1);
#pragma unroll
            for (int nt = 0; nt < 4; nt++) {
#pragma unroll
                for (int cc = 0; cc < 2; cc++) {
                    int e = e0 + wn * 32 + nt * 8 + 2 * c + cc;
                    float v = acc[mb][nt][hr * 2 + cc] + __ldg(bias + e);
                    int h   = e / 192;
                    int rem = e - h * 192;
                    int d   = rem / 3;
                    int jj  = rem - d * 3;
                    size_t idx = ((size_t)(bb * cH + h) * cN + n) * cD + d;
                    if (jj == 0)      g_q[idx] = v;
                    else if (jj == 1) g_k[idx] = v;
                    else              g_v[idx] = v;
                }
            }
        }
    }
}

// ---------------------------------------------------------------------------
// Kernel 2: attention via split-tf32 mma with RMS-norm FOLDED into the Q/K
// convert phases (each 64-d row handled by a 4-lane quad: 2 shfls for sumsq,
// rsqrt, weight-mul, then tf32 split). No separate rmsnorm kernel.
// CTA = 64 q-rows, 64-key tiles, 8 warps (2m x 4n). S: 3-term (exact);
// PV: single tf32 (~3e-4). Smem 103KB -> 2 CTAs/SM.
// ---------------------------------------------------------------------------
#define QPL 1064
#define KPL 2120
#define PPL 1064
#define VPL 2120
#define OFF_K 8512
#define OFF_P 16992
#define OFF_V 21248
#define OFF_L 25488
#define ATTN_SMEM_WORDS 25744   // 102976 bytes

__global__ __launch_bounds__(256, 2) void attn(float* __restrict__ out,
                                               const float* __restrict__ qw,
                                               const float* __restrict__ kw) {
    extern __shared__ float smA[];
    float* Qp = smA;
    float* Kp = smA + OFF_K;
    float* Pp = smA + OFF_P;
    float* Vp = smA + OFF_V;
    float* Ls = smA + OFF_L;

    const int tid  = threadIdx.x;
    const int lane = tid & 31;
    const int wrp  = tid >> 5;
    const int wm   = wrp >> 2;
    const int wn   = wrp & 3;
    const int g    = lane >> 2;
    const int c    = lane & 3;
    const int bh   = blockIdx.y;
    const int q0   = blockIdx.x * 64;
    const float* qb = g_q + (size_t)bh * cN * cD;
    const float* kb = g_k + (size_t)bh * cN * cD;
    const float* vb = g_v + (size_t)bh * cN * cD;

    const int lr  = tid >> 2;
    const int lq4 = (tid & 3) * 4;

    // Norm weights for this thread's 16 columns (reused for Q and K loads)
    float wq[4][4], wk[4][4];
#pragma unroll
    for (int rep = 0; rep < 4; rep++) {
        float4 a = *(const float4*)(qw + lq4 + rep * 16);
        wq[rep][0] = a.x; wq[rep][1] = a.y; wq[rep][2] = a.z; wq[rep][3] = a.w;
        float4 b = *(const float4*)(kw + lq4 + rep * 16);
        wk[rep][0] = b.x; wk[rep][1] = b.y; wk[rep][2] = b.z; wk[rep][3] = b.w;
    }

    // ---- Q tile: load, RMS-normalize, split-convert into A-planes (once) ----
    {
        float va[4][4];
        float ss = 0.f;
#pragma unroll
        for (int rep = 0; rep < 4; rep++) {
            float4 v = *(const float4*)(qb + (size_t)(q0 + lr) * cD + lq4 + rep * 16);
            va[rep][0] = v.x; va[rep][1] = v.y; va[rep][2] = v.z; va[rep][3] = v.w;
            ss += v.x * v.x + v.y * v.y + v.z * v.z + v.w * v.w;
        }
        ss += __shfl_xor_sync(0xffffffffu, ss, 1);
        ss += __shfl_xor_sync(0xffffffffu, ss, 2);
        float inv = rsqrtf(ss * (1.0f / cD) + 1e-6f);
        int mb = lr >> 4, gg = lr & 7, hr = (lr >> 3) & 1;
#pragma unroll
        for (int rep = 0; rep < 4; rep++) {
            int kb4 = lq4 + rep * 16;
            int kc = kb4 >> 3, kh = (kb4 >> 2) & 1;
            int j  = hr + 2 * kh;
            int wb = (kc * 4 + mb) * 33 + gg;
#pragma unroll
            for (int i = 0; i < 4; i++) {
                float val = va[rep][i] * inv * wq[rep][i];
                unsigned hb = f2tf32(val);
                unsigned lb = f2tf32(val - __uint_as_float(hb));
                Qp[j * QPL + wb + 8 * i]       = __uint_as_float(hb);
                Qp[(4 + j) * QPL + wb + 8 * i] = __uint_as_float(lb);
            }
        }
    }

    float oacc[2][2][4];
    float lsum[4];
#pragma unroll
    for (int mb = 0; mb < 2; mb++)
#pragma unroll
        for (int nt = 0; nt < 2; nt++)
#pragma unroll
            for (int i = 0; i < 4; i++) oacc[mb][nt][i] = 0.f;
#pragma unroll
    for (int i = 0; i < 4; i++) lsum[i] = 0.f;

    for (int kt = 0; kt < cN; kt += 64) {
        __syncthreads();

        // ---- K tile: load, RMS-normalize, split-convert into B-planes ----
        {
            float va[4][4];
            float ss = 0.f;
#pragma unroll
            for (int rep = 0; rep < 4; rep++) {
                float4 v = *(const float4*)(kb + (size_t)(kt + lr) * cD + lq4 + rep * 16);
                va[rep][0] = v.x; va[rep][1] = v.y; va[rep][2] = v.z; va[rep][3] = v.w;
                ss += v.x * v.x + v.y * v.y + v.z * v.z + v.w * v.w;
            }
            ss += __shfl_xor_sync(0xffffffffu, ss, 1);
            ss += __shfl_xor_sync(0xffffffffu, ss, 2);
            float inv = rsqrtf(ss * (1.0f / cD) + 1e-6f);
            int ntg = lr >> 3, gg = lr & 7;
#pragma unroll
            for (int rep = 0; rep < 4; rep++) {
                int db4 = lq4 + rep * 16;
                int kc = db4 >> 3, pl = (db4 >> 2) & 1;
                int wb = (kc * 8 + ntg) * 33 + gg;
#pragma unroll
                for (int i = 0; i < 4; i++) {
                    float val = va[rep][i] * inv * wk[rep][i];
                    unsigned hb = f2tf32(val);
                    unsigned lb = f2tf32(val - __uint_as_float(hb));
                    Kp[pl * KPL + wb + 8 * i]       = __uint_as_float(hb);
                    Kp[(2 + pl) * KPL + wb + 8 * i] = __uint_as_float(lb);
                }
            }
        }
        // ---- V tile -> B-planes single (n=d, k=key) ----
#pragma unroll
        for (int rep = 0; rep < 4; rep++) {
            int db4 = lq4 + rep * 16;
            float4 v = *(const float4*)(vb + (size_t)(kt + lr) * cD + db4);
            float va[4] = {v.x, v.y, v.z, v.w};
            int kc = lr >> 3, ik = lr & 3, pl = (lr >> 2) & 1;
            int wb = (kc * 8 + (db4 >> 3)) * 33 + (db4 & 7) + 8 * ik;
#pragma unroll
            for (int t = 0; t < 4; t++)
                Vp[pl * VPL + wb + t] = __uint_as_float(f2tf32(va[t]));
        }
        __syncthreads();

        // ---- S = Q K^T (3-term split tf32) ----
        float sacc[2][2][4];
#pragma unroll
        for (int mb = 0; mb < 2; mb++)
#pragma unroll
            for (int nt = 0; nt < 2; nt++)
#pragma unroll
                for (int i = 0; i < 4; i++) sacc[mb][nt][i] = 0.f;

#pragma unroll
        for (int kc = 0; kc < 8; kc++) {
            unsigned bh0[2], bh1[2], bl0[2], bl1[2];
#pragma unroll
            for (int nt = 0; nt < 2; nt++) {
                int off = (kc * 8 + wn * 2 + nt) * 33 + g + 8 * c;
                bh0[nt] = __float_as_uint(Kp[off]);
                bh1[nt] = __float_as_uint(Kp[KPL + off]);
                bl0[nt] = __float_as_uint(Kp[2 * KPL + off]);
                bl1[nt] = __float_as_uint(Kp[3 * KPL + off]);
            }
#pragma unroll
            for (int mb = 0; mb < 2; mb++) {
                int aoff = (kc * 4 + wm * 2 + mb) * 33 + c * 8 + g;
                unsigned ah[4], al[4];
#pragma unroll
                for (int j = 0; j < 4; j++) {
                    ah[j] = __float_as_uint(Qp[j * QPL + aoff]);
                    al[j] = __float_as_uint(Qp[(4 + j) * QPL + aoff]);
                }
#pragma unroll
                for (int nt = 0; nt < 2; nt++) {
                    mma_tf32(sacc[mb][nt], ah, bh0[nt], bh1[nt]);
                    mma_tf32(sacc[mb][nt], ah, bl0[nt], bl1[nt]);
                    mma_tf32(sacc[mb][nt], al, bh0[nt], bh1[nt]);
                }
            }
        }

        // ---- P = exp(S/8): lsum (unrounded) + tf32 P into A-planes ----
#pragma unroll
        for (int mb = 0; mb < 2; mb++) {
#pragma unroll
            for (int nt = 0; nt < 2; nt++) {
                int blk = ((wn * 2 + nt) * 4 + wm * 2 + mb) * 33 + g;
#pragma unroll
                for (int e = 0; e < 4; e++) {
                    int hr = e >> 1, cc = e & 1;
                    float p = __expf(sacc[mb][nt][e] * 0.125f);
                    lsum[mb * 2 + hr] += p;
                    int nlow = 2 * c + cc;
                    int j  = hr + 2 * (nlow >> 2);
                    Pp[j * PPL + blk + 8 * (nlow & 3)] =
                        __uint_as_float(f2tf32(p));
                }
            }
        }
        __syncthreads();

        // ---- O += P * V (single-term tf32) ----
#pragma unroll
        for (int kc = 0; kc < 8; kc++) {
            unsigned vb0[2], vb1[2];
#pragma unroll
            for (int nt = 0; nt < 2; nt++) {
                int off = (kc * 8 + wn * 2 + nt) * 33 + g + 8 * c;
                vb0[nt] = __float_as_uint(Vp[off]);
                vb1[nt] = __float_as_uint(Vp[VPL + off]);
            }
#pragma unroll
            for (int mb = 0; mb < 2; mb++) {
                int aoff = (kc * 4 + wm * 2 + mb) * 33 + c * 8 + g;
                unsigned ap[4];
#pragma unroll
                for (int j = 0; j < 4; j++)
                    ap[j] = __float_as_uint(Pp[j * PPL + aoff]);
#pragma unroll
                for (int nt = 0; nt < 2; nt++)
                    mma_tf32(oacc[mb][nt], ap, vb0[nt], vb1[nt]);
            }
        }
    }

    // ---- lsum: reduce over c lanes, combine across n-warps via smem ----
#pragma unroll
    for (int r = 0; r < 4; r++) {
        lsum[r] += __shfl_xor_sync(0xffffffffu, lsum[r], 1);
        lsum[r] += __shfl_xor_sync(0xffffffffu, lsum[r], 2);
    }
    if (c == 0) {
#pragma unroll
        for (int mb = 0; mb < 2; mb++)
#pragma unroll
            for (int hr = 0; hr < 2; hr++) {
                int row = wm * 32 + mb * 16 + g + hr * 8;
                Ls[wn * 64 + row] = lsum[mb * 2 + hr];
            }
    }
    __syncthreads();

    // ---- write out: out[b][q0+row][h*64 + d] ----
    int bb = bh >> 4;
    int h  = bh & 15;
#pragma unroll
    for (int mb = 0; mb < 2; mb++) {
#pragma unroll
        for (int hr = 0; hr < 2; hr++) {
            int row = wm * 32 + mb * 16 + g + hr * 8;
            float lt = Ls[row] + Ls[64 + row] + Ls[128 + row] + Ls[192 + row];
            float inv = 1.0f / lt;
            size_t base = ((size_t)(bb * cN + q0 + row)) * cDIM + h * cD;
#pragma unroll
            for (int nt = 0; nt < 2; nt++) {
                int d = wn * 16 + nt * 8 + 2 * c;
                float2 r2;
                r2.x = oacc[mb][nt][hr * 2 + 0] * inv;
                r2.y = oacc[mb][nt][hr * 2 + 1] * inv;
                *(float2*)(out + base + d) = r2;
            }
        }
    }
}

// ---------------------------------------------------------------------------
extern "C" void kernel_launch(void* const* d_in, const int* in_sizes, int n_in,
                              void* d_out, int out_size) {
    const float* x        = (const float*)d_in[0];
    const float* qkv_w    = (const float*)d_in[1];
    const float* qkv_b    = (const float*)d_in[2];
    const float* q_norm_w = (const float*)d_in[3];
    const float* k_norm_w = (const float*)d_in[4];
    float* out = (float*)d_out;

    const int gemm_smem = 2 * GBUF * (int)sizeof(float);          // 69376 B
    const int attn_smem = ATTN_SMEM_WORDS * (int)sizeof(float);   // 102976 B

    // Idempotent, not stream ops (graph-capture safe); no static guards.
    cudaFuncSetAttribute(qkv_gemm, cudaFuncAttributeMaxDynamicSharedMemorySize,
                         gemm_smem);
    cudaFuncSetAttribute(attn, cudaFuncAttributeMaxDynamicSharedMemorySize,
                         attn_smem);

    dim3 g1(cE / 128, cM / 128);         // 24 x 32
    qkv_gemm<<<g1, 256, gemm_smem>>>(x, qkv_w, qkv_b);

    dim3 g3(cN / 64, cB * cH);           // 32 x 32
    attn<<<g3, 256, attn_smem>>>(out, q_norm_w, k_norm_w);
}